// round 16
// baseline (speedup 1.0000x reference)
#include <cuda_runtime.h>
#include <cuda_fp16.h>
#include <cstdint>

// ---------------- problem dims ----------------
#define NB 8192
#define NF 2048
#define NE 16
#define NU 2048
#define NDM 2048
#define NH 16
#define QS (3 * NDM)   // fused QKV row stride

// ---------------- device scratch (static, no allocations) ----------------
__device__ __half g_xh  [(size_t)NB * NF];
__device__ __half g_moeh[(size_t)NB * NU];
__device__ __half g_p0h [(size_t)NB * NU];
__device__ __half g_p1h [(size_t)NB * NU];
__device__ __half g_qkvh[(size_t)NB * QS];
__device__ __half g_atth[(size_t)NB * NDM];
__device__ __half g_ewh [(size_t)NE * NF * NU];   // fp16 expert weights, native [E][F][U]
__device__ __half g_wqkv[(size_t)NU * QS];        // fused [U][3*D] fp16
__device__ __half g_woh [(size_t)NDM * NDM];
__device__ float  g_bqkv[QS];
__device__ int    g_counts[NE];
__device__ int    g_rows [NE * NB];
__device__ float  g_gates[NE * NB];
__device__ unsigned char g_slots[NE * NB];

// ---------------- helpers ----------------
__device__ __forceinline__ uint32_t smem_u32(const void* p) {
    return (uint32_t)__cvta_generic_to_shared(p);
}
#define CPA16(dst, src) \
    asm volatile("cp.async.cg.shared.global [%0], [%1], 16;" :: "r"(dst), "l"(src))

__device__ __forceinline__ void mma16(float* c, const uint32_t* a, const uint32_t* b) {
    asm volatile(
        "mma.sync.aligned.m16n8k16.row.col.f32.f16.f16.f32 "
        "{%0,%1,%2,%3},{%4,%5,%6,%7},{%8,%9},{%0,%1,%2,%3};"
        : "+f"(c[0]), "+f"(c[1]), "+f"(c[2]), "+f"(c[3])
        : "r"(a[0]), "r"(a[1]), "r"(a[2]), "r"(a[3]), "r"(b[0]), "r"(b[1]));
}

#define LDSM4(r, addr) \
    asm volatile("ldmatrix.sync.aligned.m8n8.x4.shared.b16 {%0,%1,%2,%3}, [%4];" \
                 : "=r"((r)[0]), "=r"((r)[1]), "=r"((r)[2]), "=r"((r)[3]) : "r"(addr))
#define LDSM4T(r, addr) \
    asm volatile("ldmatrix.sync.aligned.m8n8.x4.trans.shared.b16 {%0,%1,%2,%3}, [%4];" \
                 : "=r"((r)[0]), "=r"((r)[1]), "=r"((r)[2]), "=r"((r)[3]) : "r"(addr))

// ---------------- prep kernels ----------------
__global__ void prep_kernel() {
    if (threadIdx.x < NE) g_counts[threadIdx.x] = 0;
}

// fp32 -> fp16 streaming convert
__global__ void cvt_kernel(const float* __restrict__ src, __half* __restrict__ dst, size_t n4) {
    const float4* s = (const float4*)src;
    uint2* d = (uint2*)dst;
    for (size_t i = (size_t)blockIdx.x * blockDim.x + threadIdx.x; i < n4;
         i += (size_t)gridDim.x * blockDim.x) {
        float4 v = s[i];
        __half2 lo = __floats2half2_rn(v.x, v.y);
        __half2 hi = __floats2half2_rn(v.z, v.w);
        uint2 o;
        o.x = *(uint32_t*)&lo;
        o.y = *(uint32_t*)&hi;
        d[i] = o;
    }
}

// fp32 [R][C] -> fp16 dst[r][dst_off + c] with dst row stride dld (concat converts)
__global__ void cvt_stride_kernel(const float* __restrict__ src, __half* __restrict__ dst,
                                  int R, int C, int dld, int dst_off) {
    size_t n4 = (size_t)R * C / 4;
    const float4* s = (const float4*)src;
    for (size_t i = (size_t)blockIdx.x * blockDim.x + threadIdx.x; i < n4;
         i += (size_t)gridDim.x * blockDim.x) {
        float4 v = s[i];
        size_t el = i * 4;
        int r = (int)(el / C), c = (int)(el % C);
        __half2 lo = __floats2half2_rn(v.x, v.y);
        __half2 hi = __floats2half2_rn(v.z, v.w);
        uint2 o;
        o.x = *(uint32_t*)&lo;
        o.y = *(uint32_t*)&hi;
        *(uint2*)(dst + (size_t)r * dld + dst_off + c) = o;
    }
}

__global__ void bias_concat_kernel(const float* __restrict__ b0, const float* __restrict__ b1,
                                   const float* __restrict__ b2) {
    int i = blockIdx.x * blockDim.x + threadIdx.x;
    if (i < NDM) {
        g_bqkv[i] = b0[i];
        g_bqkv[NDM + i] = b1[i];
        g_bqkv[2 * NDM + i] = b2[i];
    }
}

// combine fp16 MoE partial slots -> fp16 A operand for QKV GEMM (fp32 add)
__global__ void combine_kernel() {
    size_t n = (size_t)NB * NU / 8;   // 8 halves per iter
    const uint4* a = (const uint4*)g_p0h;
    const uint4* b = (const uint4*)g_p1h;
    uint4* d = (uint4*)g_moeh;
    for (size_t i = (size_t)blockIdx.x * blockDim.x + threadIdx.x; i < n;
         i += (size_t)gridDim.x * blockDim.x) {
        uint4 u = a[i], w = b[i];
        uint4 o;
        const uint32_t* up = &u.x;
        const uint32_t* wp = &w.x;
        uint32_t* op = &o.x;
#pragma unroll
        for (int j = 0; j < 4; j++) {
            float2 uf = __half22float2(*(const __half2*)&up[j]);
            float2 wf = __half22float2(*(const __half2*)&wp[j]);
            __half2 r = __floats2half2_rn(uf.x + wf.x, uf.y + wf.y);
            op[j] = *(uint32_t*)&r;
        }
        d[i] = o;
    }
}

// ---------------- router: fp32 logits, softmax, top-2 + fused x->fp16 ----------------
__global__ void router_kernel(const float* __restrict__ x,
                              const float* __restrict__ rw,
                              const float* __restrict__ rb) {
    const int b = blockIdx.x;
    const int tid = threadIdx.x;  // 128 threads
    float part[NE];
#pragma unroll
    for (int e = 0; e < NE; e++) part[e] = 0.f;

    const float* xr = x + (size_t)b * NF;
    __half* xh = g_xh + (size_t)b * NF;
    for (int f = tid; f < NF; f += 128) {
        float xv = xr[f];
        xh[f] = __float2half_rn(xv);
        const float4* w4 = (const float4*)(rw + (size_t)f * NE);
#pragma unroll
        for (int e4 = 0; e4 < 4; e4++) {
            float4 w = w4[e4];
            part[e4 * 4 + 0] += xv * w.x;
            part[e4 * 4 + 1] += xv * w.y;
            part[e4 * 4 + 2] += xv * w.z;
            part[e4 * 4 + 3] += xv * w.w;
        }
    }

    __shared__ float red[NE][128];
#pragma unroll
    for (int e = 0; e < NE; e++) red[e][tid] = part[e];
    __syncthreads();

    __shared__ float lg[NE];
    if (tid < NE) {
        float s = 0.f;
        for (int j = 0; j < 128; j++) s += red[tid][j];
        lg[tid] = s + rb[tid];
    }
    __syncthreads();

    if (tid == 0) {
        float mx = lg[0];
#pragma unroll
        for (int e = 1; e < NE; e++) mx = fmaxf(mx, lg[e]);
        float p[NE];
        float s = 0.f;
#pragma unroll
        for (int e = 0; e < NE; e++) { p[e] = expf(lg[e] - mx); s += p[e]; }
        int e0 = 0; float b0 = p[0];
#pragma unroll
        for (int e = 1; e < NE; e++) if (p[e] > b0) { b0 = p[e]; e0 = e; }
        int e1 = -1; float b1 = -1.f;
#pragma unroll
        for (int e = 0; e < NE; e++)
            if (e != e0 && p[e] > b1) { b1 = p[e]; e1 = e; }
        float inv = 1.f / s;
        int pos = atomicAdd(&g_counts[e0], 1);
        g_rows [e0 * NB + pos] = b;
        g_gates[e0 * NB + pos] = b0 * inv;
        g_slots[e0 * NB + pos] = 0;
        pos = atomicAdd(&g_counts[e1], 1);
        g_rows [e1 * NB + pos] = b;
        g_gates[e1 * NB + pos] = b1 * inv;
        g_slots[e1 * NB + pos] = 1;
    }
}

// ---------------- fp16 GEMM: 128x128x64, 4 warps x (64x64), 3-stage multistage -----
// warp tile 64x64 halves smem fragment duplication (A 2x, B 2x vs 4x/2x)
#define BM 128
#define BN 128
#define BKK 64
#define STG 3
#define LDA 72        // halves/row (144B): LDSM phases r%8, distinct
#define LDB2 136      // halves/row (272B): r*17%8 = r%8, distinct
#define NTHREADS 128
#define NKITER (NF / BKK)  // 32
#define A_STAGE (BM * LDA * 2)          // 18432
#define B_STAGE (BKK * LDB2 * 2)        // 17408
#define A_BYTES (STG * A_STAGE)         // 55296
#define DYN_SMEM (STG * (A_STAGE + B_STAGE))  // 107520 -> 2 CTAs/SM

// MOE: gather A rows, gate*relu(acc+bias) -> fp16 slot buffers
// !MOE: C = A@B + bias; HOUT selects fp16 vs fp32 C
template <bool MOE, bool HOUT>
__global__ __launch_bounds__(NTHREADS) void gemm_kernel(
    const __half* __restrict__ A, const __half* __restrict__ B,
    const float* __restrict__ bias, void* __restrict__ Cv,
    int ldb, int ldc) {
    extern __shared__ char smraw[];
    char* smA = smraw;
    char* smB = smraw + A_BYTES;
    __shared__ int rows_s[BM];
    __shared__ float gate_s[BM];
    __shared__ int slot_s[BM];

    const int tid = threadIdx.x;
    const int n0blk = blockIdx.x * BN;
    const int m0blk = blockIdx.y * BM;

    int cnt = BM;
    const __half* Bp = B;
    const float* biasp = bias;
    if (MOE) {
        const int e = blockIdx.z;
        const int ce = g_counts[e];
        cnt = ce - m0blk;
        if (cnt <= 0) return;
        if (cnt > BM) cnt = BM;
        Bp = B + (size_t)e * NF * NU;
        biasp = bias + e * NU;
        {
            bool v = tid < cnt;
            rows_s[tid] = v ? g_rows [e * NB + m0blk + tid] : 0;
            gate_s[tid] = v ? g_gates[e * NB + m0blk + tid] : 0.f;
            slot_s[tid] = v ? (int)g_slots[e * NB + m0blk + tid] : 0;
        }
        __syncthreads();
    }

    const int lane = tid & 31, warp = tid >> 5;   // 4 warps
    const int wm = (warp & 1) * 64;               // 2 warps in M
    const int wn = (warp >> 1) * 64;              // 2 warps in N
    const int g = lane >> 2, tig = lane & 3;

    const int l15 = lane & 15;
    const int lhi = (lane >> 4) * 8;
    const uint32_t baseA = smem_u32(smA);
    const uint32_t baseB = smem_u32(smB);
    const uint32_t aoff = ((wm + l15) * LDA + lhi) * 2;
    const uint32_t boff = (l15 * LDB2 + wn + lhi) * 2;

    float acc[4][8][4];
#pragma unroll
    for (int mt = 0; mt < 4; mt++)
#pragma unroll
        for (int nt = 0; nt < 8; nt++)
#pragma unroll
            for (int i = 0; i < 4; i++) acc[mt][nt][i] = 0.f;

    // A stage: 1024 x 16B chunks -> 8 per thread; B stage: 1024 chunks -> 8 per thread
    auto loadA = [&](int buf, int k0) {
#pragma unroll
        for (int i = 0; i < 8; i++) {
            int c = tid + i * NTHREADS;
            int m = c >> 3, hc = (c & 7) * 8;
            const __half* src;
            if (MOE) src = A + (size_t)rows_s[m] * NF + k0 + hc;
            else     src = A + (size_t)(m0blk + m) * NF + k0 + hc;
            CPA16(smem_u32(smA + buf * A_STAGE + (m * LDA + hc) * 2), src);
        }
    };
    auto loadB = [&](int buf, int k0) {
#pragma unroll
        for (int i = 0; i < 8; i++) {
            int c = tid + i * NTHREADS;
            int kr = c >> 4, nc = (c & 15) * 8;
            CPA16(smem_u32(smB + buf * B_STAGE + (kr * LDB2 + nc) * 2),
                  Bp + (size_t)(k0 + kr) * ldb + n0blk + nc);
        }
    };

    // prologue: stages 0 and 1 in flight (load distance 2)
    loadA(0, 0); loadB(0, 0);
    asm volatile("cp.async.commit_group;");
    loadA(1, BKK); loadB(1, BKK);
    asm volatile("cp.async.commit_group;");

    int cs = 0, ls = 2;
    for (int kt = 0; kt < NKITER; kt++) {
        asm volatile("cp.async.wait_group 1;");
        __syncthreads();   // single barrier per iteration

        const uint32_t abase = baseA + cs * A_STAGE + aoff;
        const uint32_t bbase = baseB + cs * B_STAGE + boff;
#pragma unroll
        for (int ks = 0; ks < 4; ks++) {
            uint32_t a[4][4], b[4][4];
#pragma unroll
            for (int mt = 0; mt < 4; mt++)
                LDSM4(a[mt], abase + (mt * 16 * LDA + ks * 16) * 2);
#pragma unroll
            for (int ntp = 0; ntp < 4; ntp++)
                LDSM4T(b[ntp], bbase + (ks * 16 * LDB2 + ntp * 16) * 2);
#pragma unroll
            for (int mt = 0; mt < 4; mt++)
#pragma unroll
                for (int nt = 0; nt < 8; nt++)
                    mma16(acc[mt][nt], a[mt], &b[nt >> 1][(nt & 1) * 2]);
        }

        // issue global loads for stage kt+2 AFTER compute (single-barrier safe)
        if (kt + 2 < NKITER) {
            loadA(ls, (kt + 2) * BKK);
            loadB(ls, (kt + 2) * BKK);
        }
        asm volatile("cp.async.commit_group;");

        cs = (cs + 1 == STG) ? 0 : cs + 1;
        ls = (ls + 1 == STG) ? 0 : ls + 1;
    }

#pragma unroll
    for (int mt = 0; mt < 4; mt++) {
#pragma unroll
        for (int nt = 0; nt < 8; nt++) {
            int r0 = wm + mt * 16 + g;
            int r1 = r0 + 8;
            int cg0 = n0blk + wn + nt * 8 + 2 * tig;
            int cg1 = cg0 + 1;
            float bz0 = biasp[cg0], bz1 = biasp[cg1];
            if (MOE) {
                if (r0 < cnt) {
                    int tok = rows_s[r0]; float gt = gate_s[r0];
                    __half* dst = (slot_s[r0] ? g_p1h : g_p0h) + (size_t)tok * NU;
                    __half2 o = __floats2half2_rn(
                        gt * fmaxf(acc[mt][nt][0] + bz0, 0.f),
                        gt * fmaxf(acc[mt][nt][1] + bz1, 0.f));
                    *(__half2*)(dst + cg0) = o;
                }
                if (r1 < cnt) {
                    int tok = rows_s[r1]; float gt = gate_s[r1];
                    __half* dst = (slot_s[r1] ? g_p1h : g_p0h) + (size_t)tok * NU;
                    __half2 o = __floats2half2_rn(
                        gt * fmaxf(acc[mt][nt][2] + bz0, 0.f),
                        gt * fmaxf(acc[mt][nt][3] + bz1, 0.f));
                    *(__half2*)(dst + cg0) = o;
                }
            } else if (HOUT) {
                __half* C = (__half*)Cv;
                size_t ro0 = (size_t)(m0blk + r0) * ldc;
                size_t ro1 = (size_t)(m0blk + r1) * ldc;
                *(__half2*)(C + ro0 + cg0) =
                    __floats2half2_rn(acc[mt][nt][0] + bz0, acc[mt][nt][1] + bz1);
                *(__half2*)(C + ro1 + cg0) =
                    __floats2half2_rn(acc[mt][nt][2] + bz0, acc[mt][nt][3] + bz1);
            } else {
                float* C = (float*)Cv;
                size_t ro0 = (size_t)(m0blk + r0) * ldc;
                size_t ro1 = (size_t)(m0blk + r1) * ldc;
                C[ro0 + cg0] = acc[mt][nt][0] + bz0;
                C[ro0 + cg1] = acc[mt][nt][1] + bz1;
                C[ro1 + cg0] = acc[mt][nt][2] + bz0;
                C[ro1 + cg1] = acc[mt][nt][3] + bz1;
            }
        }
    }
}

// ---------------- per-token single-latent attention (fp16 qkv in, fp16 out) -------
__global__ void attn_kernel() {
    const int b = blockIdx.x;
    const int tid = threadIdx.x;  // 256
    const int warp = tid >> 5, lane = tid & 31;

    __shared__ float sc[NH];
    const __half* row = g_qkvh + (size_t)b * QS;
    const uint2* q4 = (const uint2*)row;               // 4 halves per elem
    const uint2* k4 = (const uint2*)(row + NDM);
    const uint2* v4 = (const uint2*)(row + 2 * NDM);
    uint2* o4 = (uint2*)(g_atth + (size_t)b * NDM);

#pragma unroll
    for (int i = 0; i < 2; i++) {
        int h = warp * 2 + i;
        uint2 qr = q4[h * 32 + lane];
        uint2 kr = k4[h * 32 + lane];
        float2 q0 = __half22float2(*(const __half2*)&qr.x);
        float2 q1 = __half22float2(*(const __half2*)&qr.y);
        float2 k0 = __half22float2(*(const __half2*)&kr.x);
        float2 k1 = __half22float2(*(const __half2*)&kr.y);
        float s = q0.x * k0.x + q0.y * k0.y + q1.x * k1.x + q1.y * k1.y;
#pragma unroll
        for (int o = 16; o; o >>= 1) s += __shfl_xor_sync(0xffffffffu, s, o);
        if (lane == 0) sc[h] = s * 0.08838834764831845f;  // 1/sqrt(128)
    }
    __syncthreads();

    float mx = sc[0];
#pragma unroll
    for (int h = 1; h < NH; h++) mx = fmaxf(mx, sc[h]);
    float ssum = 0.f;
#pragma unroll
    for (int h = 0; h < NH; h++) ssum += expf(sc[h] - mx);
    float inv = 1.f / ssum;
    float a0 = expf(sc[warp] - mx) * inv;
    float a1 = expf(sc[warp + 8] - mx) * inv;

    {
        uint2 vr = v4[tid];
        float2 v0 = __half22float2(*(const __half2*)&vr.x);
        float2 v1 = __half22float2(*(const __half2*)&vr.y);
        __half2 lo = __floats2half2_rn(a0 * v0.x, a0 * v0.y);
        __half2 hi = __floats2half2_rn(a0 * v1.x, a0 * v1.y);
        uint2 o; o.x = *(uint32_t*)&lo; o.y = *(uint32_t*)&hi;
        o4[tid] = o;
    }
    {
        uint2 vr = v4[tid + 256];
        float2 v0 = __half22float2(*(const __half2*)&vr.x);
        float2 v1 = __half22float2(*(const __half2*)&vr.y);
        __half2 lo = __floats2half2_rn(a1 * v0.x, a1 * v0.y);
        __half2 hi = __floats2half2_rn(a1 * v1.x, a1 * v1.y);
        uint2 o; o.x = *(uint32_t*)&lo; o.y = *(uint32_t*)&hi;
        o4[tid + 256] = o;
    }
}

// ---------------- launcher ----------------
extern "C" void kernel_launch(void* const* d_in, const int* in_sizes, int n_in,
                              void* d_out, int out_size) {
    const float* x  = (const float*)d_in[0];
    const float* rw = (const float*)d_in[1];
    const float* rb = (const float*)d_in[2];
    const float* ew = (const float*)d_in[3];
    const float* eb = (const float*)d_in[4];
    const float* wq = (const float*)d_in[5];
    const float* bq = (const float*)d_in[6];
    const float* wk = (const float*)d_in[7];
    const float* bk = (const float*)d_in[8];
    const float* wv = (const float*)d_in[9];
    const float* bv = (const float*)d_in[10];
    const float* wo = (const float*)d_in[11];
    const float* bo = (const float*)d_in[12];
    float* out = (float*)d_out;

    cudaFuncSetAttribute((const void*)gemm_kernel<true,  false>,
                         cudaFuncAttributeMaxDynamicSharedMemorySize, DYN_SMEM);
    cudaFuncSetAttribute((const void*)gemm_kernel<false, true>,
                         cudaFuncAttributeMaxDynamicSharedMemorySize, DYN_SMEM);
    cudaFuncSetAttribute((const void*)gemm_kernel<false, false>,
                         cudaFuncAttributeMaxDynamicSharedMemorySize, DYN_SMEM);

    __half *p_xh, *p_moeh, *p_atth, *p_ewh, *p_wqkv, *p_woh, *p_qkvh;
    float *p_bqkv;
    cudaGetSymbolAddress((void**)&p_xh,   g_xh);
    cudaGetSymbolAddress((void**)&p_moeh, g_moeh);
    cudaGetSymbolAddress((void**)&p_atth, g_atth);
    cudaGetSymbolAddress((void**)&p_ewh,  g_ewh);
    cudaGetSymbolAddress((void**)&p_wqkv, g_wqkv);
    cudaGetSymbolAddress((void**)&p_woh,  g_woh);
    cudaGetSymbolAddress((void**)&p_qkvh, g_qkvh);
    cudaGetSymbolAddress((void**)&p_bqkv, g_bqkv);

    prep_kernel<<<1, 32>>>();                                              // 1
    router_kernel<<<NB, 128>>>(x, rw, rb);                                 // 2
    cvt_kernel<<<2048, 256>>>(ew, p_ewh, (size_t)NE * NF * NU / 4);        // 3
    gemm_kernel<true, false><<<dim3(NU / BN, NB / BM, NE), NTHREADS, DYN_SMEM>>>( // 4
        p_xh, p_ewh, eb, nullptr, NU, 0);
    combine_kernel<<<2048, 256>>>();                                       // 5
    cvt_stride_kernel<<<512, 256>>>(wq, p_wqkv, NU, NDM, QS, 0);           // 6
    cvt_stride_kernel<<<512, 256>>>(wk, p_wqkv, NU, NDM, QS, NDM);         // 7
    cvt_stride_kernel<<<512, 256>>>(wv, p_wqkv, NU, NDM, QS, 2 * NDM);     // 8
    cvt_kernel<<<512, 256>>>(wo, p_woh, (size_t)NDM * NDM / 4);            // 9
    bias_concat_kernel<<<(NDM + 255) / 256, 256>>>(bq, bk, bv);            // 10

    // fused QKV GEMM: [8192 x 2048] @ [2048 x 6144] -> fp16
    gemm_kernel<false, true><<<dim3(QS / BN, NB / BM), NTHREADS, DYN_SMEM>>>(
        p_moeh, p_wqkv, p_bqkv, p_qkvh, QS, QS);

    attn_kernel<<<NB, 256>>>();

    gemm_kernel<false, false><<<dim3(NDM / BN, NB / BM), NTHREADS, DYN_SMEM>>>(
        p_atth, p_woh, bo, out, NDM, NDM);
}

// round 17
// speedup vs baseline: 1.1076x; 1.1076x over previous
#include <cuda_runtime.h>
#include <cuda_fp16.h>
#include <cstdint>

// ---------------- problem dims ----------------
#define NB 8192
#define NF 2048
#define NE 16
#define NU 2048
#define NDM 2048
#define NH 16
#define QS (3 * NDM)   // fused QKV row stride

// ---------------- device scratch (static, no allocations) ----------------
__device__ __half g_xh  [(size_t)NB * NF];
__device__ __half g_moeh[(size_t)NB * NU];
__device__ __half g_p0h [(size_t)NB * NU];
__device__ __half g_p1h [(size_t)NB * NU];
__device__ __half g_qkvh[(size_t)NB * QS];
__device__ __half g_atth[(size_t)NB * NDM];
__device__ __half g_ewh [(size_t)NE * NF * NU];   // fp16 expert weights, native [E][F][U]
__device__ __half g_wqkv[(size_t)NU * QS];        // fused [U][3*D] fp16
__device__ __half g_woh [(size_t)NDM * NDM];
__device__ float  g_bqkv[QS];
__device__ int    g_counts[NE];
__device__ int    g_rows [NE * NB];
__device__ float  g_gates[NE * NB];
__device__ unsigned char g_slots[NE * NB];

// ---------------- helpers ----------------
__device__ __forceinline__ uint32_t smem_u32(const void* p) {
    return (uint32_t)__cvta_generic_to_shared(p);
}
#define CPA16(dst, src) \
    asm volatile("cp.async.cg.shared.global [%0], [%1], 16;" :: "r"(dst), "l"(src))

__device__ __forceinline__ void mma16(float* c, const uint32_t* a, const uint32_t* b) {
    asm volatile(
        "mma.sync.aligned.m16n8k16.row.col.f32.f16.f16.f32 "
        "{%0,%1,%2,%3},{%4,%5,%6,%7},{%8,%9},{%0,%1,%2,%3};"
        : "+f"(c[0]), "+f"(c[1]), "+f"(c[2]), "+f"(c[3])
        : "r"(a[0]), "r"(a[1]), "r"(a[2]), "r"(a[3]), "r"(b[0]), "r"(b[1]));
}

#define LDSM4(r, addr) \
    asm volatile("ldmatrix.sync.aligned.m8n8.x4.shared.b16 {%0,%1,%2,%3}, [%4];" \
                 : "=r"((r)[0]), "=r"((r)[1]), "=r"((r)[2]), "=r"((r)[3]) : "r"(addr))
#define LDSM4T(r, addr) \
    asm volatile("ldmatrix.sync.aligned.m8n8.x4.trans.shared.b16 {%0,%1,%2,%3}, [%4];" \
                 : "=r"((r)[0]), "=r"((r)[1]), "=r"((r)[2]), "=r"((r)[3]) : "r"(addr))

// ---------------- prep kernels ----------------
__global__ void prep_kernel() {
    if (threadIdx.x < NE) g_counts[threadIdx.x] = 0;
}

// fp32 -> fp16 streaming convert
__global__ void cvt_kernel(const float* __restrict__ src, __half* __restrict__ dst, size_t n4) {
    const float4* s = (const float4*)src;
    uint2* d = (uint2*)dst;
    for (size_t i = (size_t)blockIdx.x * blockDim.x + threadIdx.x; i < n4;
         i += (size_t)gridDim.x * blockDim.x) {
        float4 v = s[i];
        __half2 lo = __floats2half2_rn(v.x, v.y);
        __half2 hi = __floats2half2_rn(v.z, v.w);
        uint2 o;
        o.x = *(uint32_t*)&lo;
        o.y = *(uint32_t*)&hi;
        d[i] = o;
    }
}

// fp32 [R][C] -> fp16 dst[r][dst_off + c] with dst row stride dld (concat converts)
__global__ void cvt_stride_kernel(const float* __restrict__ src, __half* __restrict__ dst,
                                  int R, int C, int dld, int dst_off) {
    size_t n4 = (size_t)R * C / 4;
    const float4* s = (const float4*)src;
    for (size_t i = (size_t)blockIdx.x * blockDim.x + threadIdx.x; i < n4;
         i += (size_t)gridDim.x * blockDim.x) {
        float4 v = s[i];
        size_t el = i * 4;
        int r = (int)(el / C), c = (int)(el % C);
        __half2 lo = __floats2half2_rn(v.x, v.y);
        __half2 hi = __floats2half2_rn(v.z, v.w);
        uint2 o;
        o.x = *(uint32_t*)&lo;
        o.y = *(uint32_t*)&hi;
        *(uint2*)(dst + (size_t)r * dld + dst_off + c) = o;
    }
}

__global__ void bias_concat_kernel(const float* __restrict__ b0, const float* __restrict__ b1,
                                   const float* __restrict__ b2) {
    int i = blockIdx.x * blockDim.x + threadIdx.x;
    if (i < NDM) {
        g_bqkv[i] = b0[i];
        g_bqkv[NDM + i] = b1[i];
        g_bqkv[2 * NDM + i] = b2[i];
    }
}

// combine fp16 MoE partial slots -> fp16 A operand for QKV GEMM (fp32 add)
__global__ void combine_kernel() {
    size_t n = (size_t)NB * NU / 8;   // 8 halves per iter
    const uint4* a = (const uint4*)g_p0h;
    const uint4* b = (const uint4*)g_p1h;
    uint4* d = (uint4*)g_moeh;
    for (size_t i = (size_t)blockIdx.x * blockDim.x + threadIdx.x; i < n;
         i += (size_t)gridDim.x * blockDim.x) {
        uint4 u = a[i], w = b[i];
        uint4 o;
        const uint32_t* up = &u.x;
        const uint32_t* wp = &w.x;
        uint32_t* op = &o.x;
#pragma unroll
        for (int j = 0; j < 4; j++) {
            float2 uf = __half22float2(*(const __half2*)&up[j]);
            float2 wf = __half22float2(*(const __half2*)&wp[j]);
            __half2 r = __floats2half2_rn(uf.x + wf.x, uf.y + wf.y);
            op[j] = *(uint32_t*)&r;
        }
        d[i] = o;
    }
}

// ---------------- router: fp32 logits, softmax, top-2 + fused x->fp16 ----------------
__global__ void router_kernel(const float* __restrict__ x,
                              const float* __restrict__ rw,
                              const float* __restrict__ rb) {
    const int b = blockIdx.x;
    const int tid = threadIdx.x;  // 128 threads
    float part[NE];
#pragma unroll
    for (int e = 0; e < NE; e++) part[e] = 0.f;

    const float* xr = x + (size_t)b * NF;
    __half* xh = g_xh + (size_t)b * NF;
    for (int f = tid; f < NF; f += 128) {
        float xv = xr[f];
        xh[f] = __float2half_rn(xv);
        const float4* w4 = (const float4*)(rw + (size_t)f * NE);
#pragma unroll
        for (int e4 = 0; e4 < 4; e4++) {
            float4 w = w4[e4];
            part[e4 * 4 + 0] += xv * w.x;
            part[e4 * 4 + 1] += xv * w.y;
            part[e4 * 4 + 2] += xv * w.z;
            part[e4 * 4 + 3] += xv * w.w;
        }
    }

    __shared__ float red[NE][128];
#pragma unroll
    for (int e = 0; e < NE; e++) red[e][tid] = part[e];
    __syncthreads();

    __shared__ float lg[NE];
    if (tid < NE) {
        float s = 0.f;
        for (int j = 0; j < 128; j++) s += red[tid][j];
        lg[tid] = s + rb[tid];
    }
    __syncthreads();

    if (tid == 0) {
        float mx = lg[0];
#pragma unroll
        for (int e = 1; e < NE; e++) mx = fmaxf(mx, lg[e]);
        float p[NE];
        float s = 0.f;
#pragma unroll
        for (int e = 0; e < NE; e++) { p[e] = expf(lg[e] - mx); s += p[e]; }
        int e0 = 0; float b0 = p[0];
#pragma unroll
        for (int e = 1; e < NE; e++) if (p[e] > b0) { b0 = p[e]; e0 = e; }
        int e1 = -1; float b1 = -1.f;
#pragma unroll
        for (int e = 0; e < NE; e++)
            if (e != e0 && p[e] > b1) { b1 = p[e]; e1 = e; }
        float inv = 1.f / s;
        int pos = atomicAdd(&g_counts[e0], 1);
        g_rows [e0 * NB + pos] = b;
        g_gates[e0 * NB + pos] = b0 * inv;
        g_slots[e0 * NB + pos] = 0;
        pos = atomicAdd(&g_counts[e1], 1);
        g_rows [e1 * NB + pos] = b;
        g_gates[e1 * NB + pos] = b1 * inv;
        g_slots[e1 * NB + pos] = 1;
    }
}

// ---------------- fp16 GEMM: 128x128x64, 3-stage multistage + frag double-buffer ---
// (round-15 config: best profiled GEMM — tensor 61.4%, 386us on MoE)
#define BM 128
#define BN 128
#define BKK 64
#define STG 3
#define LDA 72        // halves/row (144B): LDSM phases r%8, distinct
#define LDB2 136      // halves/row (272B): r*17%8 = r%8, distinct
#define NTHREADS 256
#define NKITER (NF / BKK)  // 32
#define A_STAGE (BM * LDA * 2)          // 18432
#define B_STAGE (BKK * LDB2 * 2)        // 17408
#define A_BYTES (STG * A_STAGE)         // 55296
#define DYN_SMEM (STG * (A_STAGE + B_STAGE))  // 107520 -> 2 CTAs/SM

// MOE: gather A rows, gate*relu(acc+bias) -> fp16 slot buffers
// !MOE: C = A@B + bias; HOUT selects fp16 vs fp32 C
template <bool MOE, bool HOUT>
__global__ __launch_bounds__(NTHREADS, 2) void gemm_kernel(
    const __half* __restrict__ A, const __half* __restrict__ B,
    const float* __restrict__ bias, void* __restrict__ Cv,
    int ldb, int ldc) {
    extern __shared__ char smraw[];
    char* smA = smraw;
    char* smB = smraw + A_BYTES;
    __shared__ int rows_s[BM];
    __shared__ float gate_s[BM];
    __shared__ int slot_s[BM];

    const int tid = threadIdx.x;
    const int n0blk = blockIdx.x * BN;
    const int m0blk = blockIdx.y * BM;

    int cnt = BM;
    const __half* Bp = B;
    const float* biasp = bias;
    if (MOE) {
        const int e = blockIdx.z;
        const int ce = g_counts[e];
        cnt = ce - m0blk;
        if (cnt <= 0) return;
        if (cnt > BM) cnt = BM;
        Bp = B + (size_t)e * NF * NU;
        biasp = bias + e * NU;
        if (tid < BM) {
            bool v = tid < cnt;
            rows_s[tid] = v ? g_rows [e * NB + m0blk + tid] : 0;
            gate_s[tid] = v ? g_gates[e * NB + m0blk + tid] : 0.f;
            slot_s[tid] = v ? (int)g_slots[e * NB + m0blk + tid] : 0;
        }
        __syncthreads();
    }

    const int lane = tid & 31, warp = tid >> 5;
    const int wm = (warp >> 2) * 64;
    const int wn = (warp & 3) * 32;
    const int g = lane >> 2, tig = lane & 3;

    const int l15 = lane & 15;
    const int lhi = (lane >> 4) * 8;
    const uint32_t baseA = smem_u32(smA);
    const uint32_t baseB = smem_u32(smB);
    const uint32_t aoff = ((wm + l15) * LDA + lhi) * 2;
    const uint32_t boff = (l15 * LDB2 + wn + lhi) * 2;

    float acc[4][4][4];
#pragma unroll
    for (int mt = 0; mt < 4; mt++)
#pragma unroll
        for (int nt = 0; nt < 4; nt++)
#pragma unroll
            for (int i = 0; i < 4; i++) acc[mt][nt][i] = 0.f;

    auto loadA = [&](int buf, int k0) {
#pragma unroll
        for (int i = 0; i < 4; i++) {
            int c = tid + i * NTHREADS;
            int m = c >> 3, hc = (c & 7) * 8;
            const __half* src;
            if (MOE) src = A + (size_t)rows_s[m] * NF + k0 + hc;
            else     src = A + (size_t)(m0blk + m) * NF + k0 + hc;
            CPA16(smem_u32(smA + buf * A_STAGE + (m * LDA + hc) * 2), src);
        }
    };
    auto loadB = [&](int buf, int k0) {
#pragma unroll
        for (int i = 0; i < 4; i++) {
            int c = tid + i * NTHREADS;
            int kr = c >> 4, nc = (c & 15) * 8;
            CPA16(smem_u32(smB + buf * B_STAGE + (kr * LDB2 + nc) * 2),
                  Bp + (size_t)(k0 + kr) * ldb + n0blk + nc);
        }
    };

    // prologue: stages 0 and 1 in flight (load distance 2)
    loadA(0, 0); loadB(0, 0);
    asm volatile("cp.async.commit_group;");
    loadA(1, BKK); loadB(1, BKK);
    asm volatile("cp.async.commit_group;");

    // double-buffered register fragments
    uint32_t afr[2][4][4], bfr[2][2][4];

    int cs = 0, ls = 2;
    for (int kt = 0; kt < NKITER; kt++) {
        asm volatile("cp.async.wait_group 1;");
        __syncthreads();   // single barrier per iteration

        const uint32_t abase = baseA + cs * A_STAGE + aoff;
        const uint32_t bbase = baseB + cs * B_STAGE + boff;

        // load fragments for ks = 0
#pragma unroll
        for (int mt = 0; mt < 4; mt++)
            LDSM4(afr[0][mt], abase + (mt * 16 * LDA) * 2);
#pragma unroll
        for (int ntp = 0; ntp < 2; ntp++)
            LDSM4T(bfr[0][ntp], bbase + (ntp * 16) * 2);

#pragma unroll
        for (int ks = 0; ks < 4; ks++) {
            const int cur = ks & 1, nxt = cur ^ 1;
            if (ks < 3) {
                // prefetch fragments for ks+1 while computing ks
#pragma unroll
                for (int mt = 0; mt < 4; mt++)
                    LDSM4(afr[nxt][mt], abase + (mt * 16 * LDA + (ks + 1) * 16) * 2);
#pragma unroll
                for (int ntp = 0; ntp < 2; ntp++)
                    LDSM4T(bfr[nxt][ntp], bbase + ((ks + 1) * 16 * LDB2 + ntp * 16) * 2);
            }
#pragma unroll
            for (int mt = 0; mt < 4; mt++)
#pragma unroll
                for (int nt = 0; nt < 4; nt++)
                    mma16(acc[mt][nt], afr[cur][mt], &bfr[cur][nt >> 1][(nt & 1) * 2]);
        }

        // issue global loads for stage kt+2 AFTER compute (single-barrier safe)
        if (kt + 2 < NKITER) {
            loadA(ls, (kt + 2) * BKK);
            loadB(ls, (kt + 2) * BKK);
        }
        asm volatile("cp.async.commit_group;");

        cs = (cs + 1 == STG) ? 0 : cs + 1;
        ls = (ls + 1 == STG) ? 0 : ls + 1;
    }

#pragma unroll
    for (int mt = 0; mt < 4; mt++) {
#pragma unroll
        for (int nt = 0; nt < 4; nt++) {
            int r0 = wm + mt * 16 + g;
            int r1 = r0 + 8;
            int cg0 = n0blk + wn + nt * 8 + 2 * tig;
            int cg1 = cg0 + 1;
            float bz0 = biasp[cg0], bz1 = biasp[cg1];
            if (MOE) {
                if (r0 < cnt) {
                    int tok = rows_s[r0]; float gt = gate_s[r0];
                    __half* dst = (slot_s[r0] ? g_p1h : g_p0h) + (size_t)tok * NU;
                    __half2 o = __floats2half2_rn(
                        gt * fmaxf(acc[mt][nt][0] + bz0, 0.f),
                        gt * fmaxf(acc[mt][nt][1] + bz1, 0.f));
                    *(__half2*)(dst + cg0) = o;
                }
                if (r1 < cnt) {
                    int tok = rows_s[r1]; float gt = gate_s[r1];
                    __half* dst = (slot_s[r1] ? g_p1h : g_p0h) + (size_t)tok * NU;
                    __half2 o = __floats2half2_rn(
                        gt * fmaxf(acc[mt][nt][2] + bz0, 0.f),
                        gt * fmaxf(acc[mt][nt][3] + bz1, 0.f));
                    *(__half2*)(dst + cg0) = o;
                }
            } else if (HOUT) {
                __half* C = (__half*)Cv;
                size_t ro0 = (size_t)(m0blk + r0) * ldc;
                size_t ro1 = (size_t)(m0blk + r1) * ldc;
                *(__half2*)(C + ro0 + cg0) =
                    __floats2half2_rn(acc[mt][nt][0] + bz0, acc[mt][nt][1] + bz1);
                *(__half2*)(C + ro1 + cg0) =
                    __floats2half2_rn(acc[mt][nt][2] + bz0, acc[mt][nt][3] + bz1);
            } else {
                float* C = (float*)Cv;
                size_t ro0 = (size_t)(m0blk + r0) * ldc;
                size_t ro1 = (size_t)(m0blk + r1) * ldc;
                C[ro0 + cg0] = acc[mt][nt][0] + bz0;
                C[ro0 + cg1] = acc[mt][nt][1] + bz1;
                C[ro1 + cg0] = acc[mt][nt][2] + bz0;
                C[ro1 + cg1] = acc[mt][nt][3] + bz1;
            }
        }
    }
}

// ---------------- per-token single-latent attention (fp16 qkv in, fp16 out) -------
__global__ void attn_kernel() {
    const int b = blockIdx.x;
    const int tid = threadIdx.x;  // 256
    const int warp = tid >> 5, lane = tid & 31;

    __shared__ float sc[NH];
    const __half* row = g_qkvh + (size_t)b * QS;
    const uint2* q4 = (const uint2*)row;               // 4 halves per elem
    const uint2* k4 = (const uint2*)(row + NDM);
    const uint2* v4 = (const uint2*)(row + 2 * NDM);
    uint2* o4 = (uint2*)(g_atth + (size_t)b * NDM);

#pragma unroll
    for (int i = 0; i < 2; i++) {
        int h = warp * 2 + i;
        uint2 qr = q4[h * 32 + lane];
        uint2 kr = k4[h * 32 + lane];
        float2 q0 = __half22float2(*(const __half2*)&qr.x);
        float2 q1 = __half22float2(*(const __half2*)&qr.y);
        float2 k0 = __half22float2(*(const __half2*)&kr.x);
        float2 k1 = __half22float2(*(const __half2*)&kr.y);
        float s = q0.x * k0.x + q0.y * k0.y + q1.x * k1.x + q1.y * k1.y;
#pragma unroll
        for (int o = 16; o; o >>= 1) s += __shfl_xor_sync(0xffffffffu, s, o);
        if (lane == 0) sc[h] = s * 0.08838834764831845f;  // 1/sqrt(128)
    }
    __syncthreads();

    float mx = sc[0];
#pragma unroll
    for (int h = 1; h < NH; h++) mx = fmaxf(mx, sc[h]);
    float ssum = 0.f;
#pragma unroll
    for (int h = 0; h < NH; h++) ssum += expf(sc[h] - mx);
    float inv = 1.f / ssum;
    float a0 = expf(sc[warp] - mx) * inv;
    float a1 = expf(sc[warp + 8] - mx) * inv;

    {
        uint2 vr = v4[tid];
        float2 v0 = __half22float2(*(const __half2*)&vr.x);
        float2 v1 = __half22float2(*(const __half2*)&vr.y);
        __half2 lo = __floats2half2_rn(a0 * v0.x, a0 * v0.y);
        __half2 hi = __floats2half2_rn(a0 * v1.x, a0 * v1.y);
        uint2 o; o.x = *(uint32_t*)&lo; o.y = *(uint32_t*)&hi;
        o4[tid] = o;
    }
    {
        uint2 vr = v4[tid + 256];
        float2 v0 = __half22float2(*(const __half2*)&vr.x);
        float2 v1 = __half22float2(*(const __half2*)&vr.y);
        __half2 lo = __floats2half2_rn(a1 * v0.x, a1 * v0.y);
        __half2 hi = __floats2half2_rn(a1 * v1.x, a1 * v1.y);
        uint2 o; o.x = *(uint32_t*)&lo; o.y = *(uint32_t*)&hi;
        o4[tid + 256] = o;
    }
}

// ---------------- launcher (graph-parallel helper branch) ----------------
extern "C" void kernel_launch(void* const* d_in, const int* in_sizes, int n_in,
                              void* d_out, int out_size) {
    const float* x  = (const float*)d_in[0];
    const float* rw = (const float*)d_in[1];
    const float* rb = (const float*)d_in[2];
    const float* ew = (const float*)d_in[3];
    const float* eb = (const float*)d_in[4];
    const float* wq = (const float*)d_in[5];
    const float* bq = (const float*)d_in[6];
    const float* wk = (const float*)d_in[7];
    const float* bk = (const float*)d_in[8];
    const float* wv = (const float*)d_in[9];
    const float* bv = (const float*)d_in[10];
    const float* wo = (const float*)d_in[11];
    const float* bo = (const float*)d_in[12];
    float* out = (float*)d_out;

    // created once on the (uncaptured) correctness call; reused during capture.
    static cudaStream_t s2 = [] {
        cudaStream_t s;
        cudaStreamCreateWithFlags(&s, cudaStreamNonBlocking);
        return s;
    }();
    static cudaEvent_t evFork = [] {
        cudaEvent_t e; cudaEventCreateWithFlags(&e, cudaEventDisableTiming); return e;
    }();
    static cudaEvent_t evRouter = [] {
        cudaEvent_t e; cudaEventCreateWithFlags(&e, cudaEventDisableTiming); return e;
    }();
    static cudaEvent_t evS2 = [] {
        cudaEvent_t e; cudaEventCreateWithFlags(&e, cudaEventDisableTiming); return e;
    }();

    cudaFuncSetAttribute((const void*)gemm_kernel<true,  false>,
                         cudaFuncAttributeMaxDynamicSharedMemorySize, DYN_SMEM);
    cudaFuncSetAttribute((const void*)gemm_kernel<false, true>,
                         cudaFuncAttributeMaxDynamicSharedMemorySize, DYN_SMEM);
    cudaFuncSetAttribute((const void*)gemm_kernel<false, false>,
                         cudaFuncAttributeMaxDynamicSharedMemorySize, DYN_SMEM);

    __half *p_xh, *p_moeh, *p_atth, *p_ewh, *p_wqkv, *p_woh, *p_qkvh;
    float *p_bqkv;
    cudaGetSymbolAddress((void**)&p_xh,   g_xh);
    cudaGetSymbolAddress((void**)&p_moeh, g_moeh);
    cudaGetSymbolAddress((void**)&p_atth, g_atth);
    cudaGetSymbolAddress((void**)&p_ewh,  g_ewh);
    cudaGetSymbolAddress((void**)&p_wqkv, g_wqkv);
    cudaGetSymbolAddress((void**)&p_woh,  g_woh);
    cudaGetSymbolAddress((void**)&p_qkvh, g_qkvh);
    cudaGetSymbolAddress((void**)&p_bqkv, g_bqkv);

    // main: prep, then fork s2
    prep_kernel<<<1, 32>>>();
    cudaEventRecord(evFork, 0);
    cudaStreamWaitEvent(s2, evFork, 0);

    // branch s2: router (-> g_counts/rows/gates/xh), then QKV/O weight converts
    router_kernel<<<NB, 128, 0, s2>>>(x, rw, rb);
    cudaEventRecord(evRouter, s2);
    cvt_stride_kernel<<<512, 256, 0, s2>>>(wq, p_wqkv, NU, NDM, QS, 0);
    cvt_stride_kernel<<<512, 256, 0, s2>>>(wk, p_wqkv, NU, NDM, QS, NDM);
    cvt_stride_kernel<<<512, 256, 0, s2>>>(wv, p_wqkv, NU, NDM, QS, 2 * NDM);
    cvt_kernel<<<512, 256, 0, s2>>>(wo, p_woh, (size_t)NDM * NDM / 4);
    bias_concat_kernel<<<(NDM + 255) / 256, 256, 0, s2>>>(bq, bk, bv);
    cudaEventRecord(evS2, s2);

    // main: expert-weight convert runs concurrently with the s2 branch
    cvt_kernel<<<2048, 256>>>(ew, p_ewh, (size_t)NE * NF * NU / 4);

    // main: MoE GEMM needs router results (join evRouter)
    cudaStreamWaitEvent(0, evRouter, 0);
    gemm_kernel<true, false><<<dim3(NU / BN, NB / BM, NE), NTHREADS, DYN_SMEM>>>(
        p_xh, p_ewh, eb, nullptr, NU, 0);
    combine_kernel<<<2048, 256>>>();

    // main: QKV GEMM needs fused weights/bias (join evS2)
    cudaStreamWaitEvent(0, evS2, 0);
    gemm_kernel<false, true><<<dim3(QS / BN, NB / BM), NTHREADS, DYN_SMEM>>>(
        p_moeh, p_wqkv, p_bqkv, p_qkvh, QS, QS);

    attn_kernel<<<NB, 256>>>();

    gemm_kernel<false, false><<<dim3(NDM / BN, NB / BM), NTHREADS, DYN_SMEM>>>(
        p_atth, p_woh, bo, out, NDM, NDM);
}